// round 7
// baseline (speedup 1.0000x reference)
#include <cuda_runtime.h>
#include <cuda_bf16.h>
#include <math.h>

// Problem constants
#define BATCH 2
#define SEQ   2048
#define HID   2048
#define NH    16
#define HD    128
#define MTOT  (BATCH*SEQ)   // 4096

// ---------------- scratch (device globals: allocation-free rule) ----------------
__device__ float g_q[BATCH*SEQ*HID];
__device__ float g_k[BATCH*SEQ*HID];
__device__ float g_v[BATCH*SEQ*HID];
__device__ float g_ctx[BATCH*SEQ*HID];
__device__ float g_sin[SEQ*HD];
__device__ float g_cos[SEQ*HD];

// ---------------- RoPE sin/cos table (double precision, tiny kernel) ------------
__global__ void sincos_table_kernel() {
    int idx = blockIdx.x * blockDim.x + threadIdx.x;   // over SEQ * HD/2
    if (idx >= SEQ * (HD / 2)) return;
    int pos = idx / (HD / 2);
    int j   = idx % (HD / 2);
    double inv = exp((-2.0 * (double)j / (double)HD) * log(10000.0));
    double ang = (double)pos * inv;
    float s = (float)sin(ang);
    float c = (float)cos(ang);
    g_sin[pos * HD + 2 * j]     = s;
    g_sin[pos * HD + 2 * j + 1] = s;
    g_cos[pos * HD + 2 * j]     = c;
    g_cos[pos * HD + 2 * j + 1] = c;
}

// ---------------- RoPE apply (q and k in-place) --------------------------------
__global__ void rope_kernel() {
    int idx = blockIdx.x * blockDim.x + threadIdx.x;
    const int total = BATCH * SEQ * HID / 2;
    if (idx >= total) return;
    int pair = idx % (HID / 2);
    int row  = idx / (HID / 2);
    int s    = row % SEQ;
    int d    = (pair * 2) % HD;
    float sn = g_sin[s * HD + d];
    float cs = g_cos[s * HD + d];
    int base = row * HID + pair * 2;
    float2 q = *(float2*)&g_q[base];
    float2 k = *(float2*)&g_k[base];
    float2 qo, ko;
    qo.x = q.x * cs - q.y * sn;  qo.y = q.y * cs + q.x * sn;
    ko.x = k.x * cs - k.y * sn;  ko.y = k.y * cs + k.x * sn;
    *(float2*)&g_q[base] = qo;
    *(float2*)&g_k[base] = ko;
}

// ---------------- bf16 split helpers --------------------------------------------
__device__ __forceinline__ void bsplit2(float x0, float x1, unsigned& hi, unsigned& lo) {
    __nv_bfloat16 h0 = __float2bfloat16_rn(x0);
    __nv_bfloat16 h1 = __float2bfloat16_rn(x1);
    float r0 = x0 - __bfloat162float(h0);
    float r1 = x1 - __bfloat162float(h1);
    __nv_bfloat16 l0 = __float2bfloat16_rn(r0);
    __nv_bfloat16 l1 = __float2bfloat16_rn(r1);
    hi = (unsigned)__bfloat16_as_ushort(h0) | ((unsigned)__bfloat16_as_ushort(h1) << 16);
    lo = (unsigned)__bfloat16_as_ushort(l0) | ((unsigned)__bfloat16_as_ushort(l1) << 16);
}

__device__ __forceinline__ void mma_bf16(float c[4], const unsigned a[4],
                                         unsigned b0, unsigned b1) {
    asm volatile(
        "mma.sync.aligned.m16n8k16.row.col.f32.bf16.bf16.f32 "
        "{%0,%1,%2,%3}, {%4,%5,%6,%7}, {%8,%9}, {%0,%1,%2,%3};"
        : "+f"(c[0]), "+f"(c[1]), "+f"(c[2]), "+f"(c[3])
        : "r"(a[0]), "r"(a[1]), "r"(a[2]), "r"(a[3]), "r"(b0), "r"(b1));
}

// ---------------- split-bf16 tensor GEMM: C = A[M,K] W[K,N] + bias --------------
// CTA tile 128x128, BK=32 (two k16 chunks), 256 threads = 8 warps (4x2).
// Fragments pre-packed in smem in mma register order:
//   A: idx = ((kc*8+mt)*32 + lane)*4 + reg   (LDS.128 per (mt,kc))
//   B: idx = ((kc*16+nt)*32 + lane)*2 + reg  (LDS.64 per (nt,kc))
__global__ __launch_bounds__(256, 1) void gemm_bf16x3_kernel(
    const float* __restrict__ A, const float* __restrict__ W,
    const float* __restrict__ bias, float* __restrict__ C,
    int M, int N, int K)
{
    __shared__ unsigned As_hi[2048], As_lo[2048];
    __shared__ unsigned Bs_hi[2048], Bs_lo[2048];

    const int tid  = threadIdx.x;
    const int warp = tid >> 5, lane = tid & 31;
    const int wr = warp >> 1, wc = warp & 1;     // 4x2 warp grid
    const int g = lane >> 2, t = lane & 3;
    const int rowBase = blockIdx.y * 128, colBase = blockIdx.x * 128;

    float acc[2][8][4];
#pragma unroll
    for (int i = 0; i < 2; i++)
#pragma unroll
        for (int j = 0; j < 8; j++)
#pragma unroll
            for (int c = 0; c < 4; c++) acc[i][j][c] = 0.f;

    // A loader: thread covers row ar, chunk akc (16 k-values = 4 float4)
    const int ar = tid >> 1, akc = tid & 1;
    const float* Aptr = A + (size_t)(rowBase + ar) * K + akc * 16;
    // B loader: slots tid and tid+256; slot s: k-row pair 2m,2m+1, cols n4..n4+3
    const float* Wp = W + colBase;

    float4 fa[4];     // A prefetch
    float4 fb[4];     // B prefetch (2 slots x 2 rows)

    auto loadA = [&](int kt) {
#pragma unroll
        for (int i = 0; i < 4; i++)
            fa[i] = *(const float4*)(Aptr + kt * 32 + i * 4);
    };
    auto loadB = [&](int kt) {
#pragma unroll
        for (int sl = 0; sl < 2; sl++) {
            int s = tid + sl * 256;
            int m = s >> 5;
            int n4 = (s & 31) * 4;
            fb[sl * 2 + 0] = *(const float4*)(Wp + (size_t)(kt * 32 + 2 * m)     * N + n4);
            fb[sl * 2 + 1] = *(const float4*)(Wp + (size_t)(kt * 32 + 2 * m + 1) * N + n4);
        }
    };
    auto storeA = [&]() {
        const int mt = ar >> 4, ri = ar & 15, ag = ri & 7;
        const int rbase = ri >> 3;
#pragma unroll
        for (int i = 0; i < 4; i++) {
            const float* p = (const float*)&fa[i];
#pragma unroll
            for (int h = 0; h < 2; h++) {
                int c = i * 2 + h;
                unsigned hi, lo;
                bsplit2(p[2 * h], p[2 * h + 1], hi, lo);
                int reg = rbase + ((c >> 2) << 1);
                int idx = ((akc * 8 + mt) * 32 + ag * 4 + (c & 3)) * 4 + reg;
                As_hi[idx] = hi;
                As_lo[idx] = lo;
            }
        }
    };
    auto storeB = [&]() {
#pragma unroll
        for (int sl = 0; sl < 2; sl++) {
            int s = tid + sl * 256;
            int m = s >> 5;
            int n4 = (s & 31) * 4;
            int kc = m >> 3, mloc = m & 7;
            int bt = mloc & 3, reg = mloc >> 2;
            const float* p0 = (const float*)&fb[sl * 2 + 0];
            const float* p1 = (const float*)&fb[sl * 2 + 1];
#pragma unroll
            for (int j = 0; j < 4; j++) {
                int n = n4 + j;
                unsigned hi, lo;
                bsplit2(p0[j], p1[j], hi, lo);
                int idx = ((kc * 16 + (n >> 3)) * 32 + (n & 7) * 4 + bt) * 2 + reg;
                Bs_hi[idx] = hi;
                Bs_lo[idx] = lo;
            }
        }
    };

    loadA(0); loadB(0);
    storeA(); storeB();
    __syncthreads();

    const int NT = K / 32;
    for (int kt = 0; kt < NT; kt++) {
        const bool more = (kt + 1 < NT);
        if (more) { loadA(kt + 1); loadB(kt + 1); }

#pragma unroll
        for (int kc = 0; kc < 2; kc++) {
            unsigned a_hi[2][4], a_lo[2][4];
#pragma unroll
            for (int mt_ = 0; mt_ < 2; mt_++) {
                int mt = wr * 2 + mt_;
                *(uint4*)a_hi[mt_] = *(const uint4*)&As_hi[((kc * 8 + mt) * 32 + lane) * 4];
                *(uint4*)a_lo[mt_] = *(const uint4*)&As_lo[((kc * 8 + mt) * 32 + lane) * 4];
            }
#pragma unroll
            for (int nt_ = 0; nt_ < 8; nt_++) {
                int nt = wc * 8 + nt_;
                uint2 bh = *(const uint2*)&Bs_hi[((kc * 16 + nt) * 32 + lane) * 2];
                uint2 bl = *(const uint2*)&Bs_lo[((kc * 16 + nt) * 32 + lane) * 2];
#pragma unroll
                for (int mt_ = 0; mt_ < 2; mt_++) {
                    mma_bf16(acc[mt_][nt_], a_hi[mt_], bh.x, bh.y);
                    mma_bf16(acc[mt_][nt_], a_hi[mt_], bl.x, bl.y);
                    mma_bf16(acc[mt_][nt_], a_lo[mt_], bh.x, bh.y);
                }
            }
        }

        if (more) {
            __syncthreads();
            storeA(); storeB();
            __syncthreads();
        }
    }

    // epilogue: bias + store
#pragma unroll
    for (int nt_ = 0; nt_ < 8; nt_++) {
        int col = colBase + wc * 64 + nt_ * 8 + 2 * t;
        float2 bv = *(const float2*)&bias[col];
#pragma unroll
        for (int mt_ = 0; mt_ < 2; mt_++) {
            int row0 = rowBase + wr * 32 + mt_ * 16 + g;
            float2 v0 = make_float2(acc[mt_][nt_][0] + bv.x, acc[mt_][nt_][1] + bv.y);
            float2 v1 = make_float2(acc[mt_][nt_][2] + bv.x, acc[mt_][nt_][3] + bv.y);
            *(float2*)&C[(size_t)row0 * N + col]       = v0;
            *(float2*)&C[(size_t)(row0 + 8) * N + col] = v1;
        }
    }
}

// ---------------- TF32 helpers --------------------------------------------------
__device__ __forceinline__ unsigned f2tf32(float f) {
    unsigned r;
    asm("cvt.rna.tf32.f32 %0, %1;" : "=r"(r) : "f"(f));
    return r;
}
__device__ __forceinline__ void mma_tf32(float c[4],
    unsigned a0, unsigned a1, unsigned a2, unsigned a3,
    unsigned b0, unsigned b1)
{
    asm volatile(
        "mma.sync.aligned.m16n8k8.row.col.f32.tf32.tf32.f32 "
        "{%0,%1,%2,%3}, {%4,%5,%6,%7}, {%8,%9}, {%0,%1,%2,%3};"
        : "+f"(c[0]), "+f"(c[1]), "+f"(c[2]), "+f"(c[3])
        : "r"(a0), "r"(a1), "r"(a2), "r"(a3), "r"(b0), "r"(b1));
}

// ---------------- Flash attention (TF32 tensor-core, online softmax) ------------
#define QROWS 128
#define KTILE 64
#define QSTR  132
#define VSTR  136
#define PSTR  68
#define FLASH_SMEM_WORDS (QROWS*QSTR + KTILE*QSTR + KTILE*VSTR + QROWS*PSTR)

__global__ __launch_bounds__(256, 1) void flash_tf32_kernel(
    const float* __restrict__ Qg, const float* __restrict__ Kg,
    const float* __restrict__ Vg, float* __restrict__ Og)
{
    extern __shared__ unsigned smu[];
    unsigned* Qs = smu;
    unsigned* Ks = Qs + QROWS * QSTR;
    unsigned* Vs = Ks + KTILE * QSTR;
    unsigned* Ps = Vs + KTILE * VSTR;

    const int tid  = threadIdx.x;
    const int warp = tid >> 5;
    const int lane = tid & 31;
    const int g    = lane >> 2;
    const int t    = lane & 3;

    const int q0   = blockIdx.x * QROWS;
    const int head = blockIdx.y;
    const int b    = blockIdx.z;
    const size_t base = ((size_t)b * SEQ) * HID + (size_t)head * HD;

    const float scale = 0.08838834764831845f;

    for (int i = tid; i < QROWS * (HD / 4); i += 256) {
        int r  = i >> 5;
        int c4 = (i & 31) * 4;
        float4 v = *(const float4*)(Qg + base + (size_t)(q0 + r) * HID + c4);
        unsigned* dst = &Qs[r * QSTR + c4];
        dst[0] = f2tf32(v.x * scale);
        dst[1] = f2tf32(v.y * scale);
        dst[2] = f2tf32(v.z * scale);
        dst[3] = f2tf32(v.w * scale);
    }

    float oacc[16][4];
#pragma unroll
    for (int i = 0; i < 16; i++)
#pragma unroll
        for (int j = 0; j < 4; j++) oacc[i][j] = 0.f;
    float m0 = -INFINITY, m1 = -INFINITY, l0 = 0.f, l1 = 0.f;

    const int rowA = 16 * warp + g;

    for (int t0 = 0; t0 < SEQ; t0 += KTILE) {
        __syncthreads();
        for (int i = tid; i < KTILE * (HD / 4); i += 256) {
            int r  = i >> 5;
            int c4 = (i & 31) * 4;
            size_t goff = base + (size_t)(t0 + r) * HID + c4;
            float4 kv = *(const float4*)(Kg + goff);
            float4 vv = *(const float4*)(Vg + goff);
            unsigned* kd = &Ks[r * QSTR + c4];
            kd[0] = f2tf32(kv.x); kd[1] = f2tf32(kv.y);
            kd[2] = f2tf32(kv.z); kd[3] = f2tf32(kv.w);
            unsigned* vd = &Vs[r * VSTR + c4];
            vd[0] = f2tf32(vv.x); vd[1] = f2tf32(vv.y);
            vd[2] = f2tf32(vv.z); vd[3] = f2tf32(vv.w);
        }
        __syncthreads();

        float sacc[8][4];
#pragma unroll
        for (int i = 0; i < 8; i++)
#pragma unroll
            for (int j = 0; j < 4; j++) sacc[i][j] = 0.f;
#pragma unroll
        for (int ks = 0; ks < 16; ks++) {
            const int k0 = ks * 8;
            unsigned a0 = Qs[rowA * QSTR + k0 + t];
            unsigned a1 = Qs[(rowA + 8) * QSTR + k0 + t];
            unsigned a2 = Qs[rowA * QSTR + k0 + t + 4];
            unsigned a3 = Qs[(rowA + 8) * QSTR + k0 + t + 4];
#pragma unroll
            for (int nt = 0; nt < 8; nt++) {
                unsigned b0 = Ks[(8 * nt + g) * QSTR + k0 + t];
                unsigned b1 = Ks[(8 * nt + g) * QSTR + k0 + t + 4];
                mma_tf32(sacc[nt], a0, a1, a2, a3, b0, b1);
            }
        }

        float mx0 = -INFINITY, mx1 = -INFINITY;
#pragma unroll
        for (int nt = 0; nt < 8; nt++) {
            mx0 = fmaxf(mx0, fmaxf(sacc[nt][0], sacc[nt][1]));
            mx1 = fmaxf(mx1, fmaxf(sacc[nt][2], sacc[nt][3]));
        }
        mx0 = fmaxf(mx0, __shfl_xor_sync(0xffffffffu, mx0, 1));
        mx0 = fmaxf(mx0, __shfl_xor_sync(0xffffffffu, mx0, 2));
        mx1 = fmaxf(mx1, __shfl_xor_sync(0xffffffffu, mx1, 1));
        mx1 = fmaxf(mx1, __shfl_xor_sync(0xffffffffu, mx1, 2));
        float mn0 = fmaxf(m0, mx0), mn1 = fmaxf(m1, mx1);
        float corr0 = __expf(m0 - mn0), corr1 = __expf(m1 - mn1);
        float sum0 = 0.f, sum1 = 0.f;
#pragma unroll
        for (int nt = 0; nt < 8; nt++) {
            float p00 = __expf(sacc[nt][0] - mn0);
            float p01 = __expf(sacc[nt][1] - mn0);
            float p10 = __expf(sacc[nt][2] - mn1);
            float p11 = __expf(sacc[nt][3] - mn1);
            sum0 += p00 + p01;
            sum1 += p10 + p11;
            unsigned* pr0 = &Ps[rowA * PSTR + 8 * nt + 2 * t];
            unsigned* pr1 = &Ps[(rowA + 8) * PSTR + 8 * nt + 2 * t];
            pr0[0] = f2tf32(p00); pr0[1] = f2tf32(p01);
            pr1[0] = f2tf32(p10); pr1[1] = f2tf32(p11);
        }
        sum0 += __shfl_xor_sync(0xffffffffu, sum0, 1);
        sum0 += __shfl_xor_sync(0xffffffffu, sum0, 2);
        sum1 += __shfl_xor_sync(0xffffffffu, sum1, 1);
        sum1 += __shfl_xor_sync(0xffffffffu, sum1, 2);
        l0 = l0 * corr0 + sum0;  m0 = mn0;
        l1 = l1 * corr1 + sum1;  m1 = mn1;
#pragma unroll
        for (int nt = 0; nt < 16; nt++) {
            oacc[nt][0] *= corr0; oacc[nt][1] *= corr0;
            oacc[nt][2] *= corr1; oacc[nt][3] *= corr1;
        }
        __syncwarp();

#pragma unroll
        for (int ks = 0; ks < 8; ks++) {
            const int k0 = ks * 8;
            unsigned a0 = Ps[rowA * PSTR + k0 + t];
            unsigned a1 = Ps[(rowA + 8) * PSTR + k0 + t];
            unsigned a2 = Ps[rowA * PSTR + k0 + t + 4];
            unsigned a3 = Ps[(rowA + 8) * PSTR + k0 + t + 4];
#pragma unroll
            for (int nt = 0; nt < 16; nt++) {
                unsigned b0 = Vs[(k0 + t) * VSTR + 8 * nt + g];
                unsigned b1 = Vs[(k0 + t + 4) * VSTR + 8 * nt + g];
                mma_tf32(oacc[nt], a0, a1, a2, a3, b0, b1);
            }
        }
    }

    const float inv0 = 1.f / l0, inv1 = 1.f / l1;
    const int grow0 = q0 + 16 * warp + g;
    const int grow1 = grow0 + 8;
#pragma unroll
    for (int nt = 0; nt < 16; nt++) {
        int col = 8 * nt + 2 * t;
        float2 v0 = make_float2(oacc[nt][0] * inv0, oacc[nt][1] * inv0);
        float2 v1 = make_float2(oacc[nt][2] * inv1, oacc[nt][3] * inv1);
        *(float2*)(Og + base + (size_t)grow0 * HID + col) = v0;
        *(float2*)(Og + base + (size_t)grow1 * HID + col) = v1;
    }
}

// ---------------- launch -------------------------------------------------------
extern "C" void kernel_launch(void* const* d_in, const int* in_sizes, int n_in,
                              void* d_out, int out_size) {
    const float* x  = (const float*)d_in[0];
    const float* Wq = (const float*)d_in[1];
    const float* bq = (const float*)d_in[2];
    const float* Wk = (const float*)d_in[3];
    const float* bk = (const float*)d_in[4];
    const float* Wv = (const float*)d_in[5];
    const float* bv = (const float*)d_in[6];
    const float* Wo = (const float*)d_in[7];
    const float* bo = (const float*)d_in[8];
    float* out = (float*)d_out;

    float *qp, *kp, *vp, *cp;
    cudaGetSymbolAddress((void**)&qp, g_q);
    cudaGetSymbolAddress((void**)&kp, g_k);
    cudaGetSymbolAddress((void**)&vp, g_v);
    cudaGetSymbolAddress((void**)&cp, g_ctx);

    {
        int n = SEQ * (HD / 2);
        sincos_table_kernel<<<(n + 255) / 256, 256>>>();
    }

    dim3 ggrid(HID / 128, MTOT / 128);   // (16, 32)
    gemm_bf16x3_kernel<<<ggrid, 256>>>(x, Wq, bq, qp, MTOT, HID, HID);
    gemm_bf16x3_kernel<<<ggrid, 256>>>(x, Wk, bk, kp, MTOT, HID, HID);
    gemm_bf16x3_kernel<<<ggrid, 256>>>(x, Wv, bv, vp, MTOT, HID, HID);

    {
        int n = BATCH * SEQ * HID / 2;
        rope_kernel<<<(n + 255) / 256, 256>>>();
    }

    const int flash_smem = FLASH_SMEM_WORDS * (int)sizeof(unsigned);  // ~167 KB
    cudaFuncSetAttribute(flash_tf32_kernel,
                         cudaFuncAttributeMaxDynamicSharedMemorySize, flash_smem);
    flash_tf32_kernel<<<dim3(SEQ / QROWS, NH, BATCH), 256, flash_smem>>>(qp, kp, vp, cp);

    gemm_bf16x3_kernel<<<ggrid, 256>>>(cp, Wo, bo, out, MTOT, HID, HID);
}

// round 9
// speedup vs baseline: 2.1695x; 2.1695x over previous
#include <cuda_runtime.h>
#include <cuda_bf16.h>
#include <math.h>

// Problem constants
#define BATCH 2
#define SEQ   2048
#define HID   2048
#define NH    16
#define HD    128
#define MTOT  (BATCH*SEQ)   // 4096
#define KP    (HID/2)       // 1024 packed k-pairs

// ---------------- scratch (device globals: allocation-free rule) ----------------
__device__ float g_q[BATCH*SEQ*HID];
__device__ float g_k[BATCH*SEQ*HID];
__device__ float g_v[BATCH*SEQ*HID];
__device__ float g_ctx[BATCH*SEQ*HID];
__device__ float g_sin[SEQ*HD];
__device__ float g_cos[SEQ*HD];
// pre-split operands (packed bf16x2 words)
__device__ unsigned g_ah[MTOT*KP];   // A hi  [M][KP]
__device__ unsigned g_al[MTOT*KP];   // A lo
__device__ unsigned g_bh[HID*KP];    // W^T hi [N][KP]
__device__ unsigned g_bl[HID*KP];    // W^T lo

// ---------------- bf16 split helper --------------------------------------------
__device__ __forceinline__ void bsplit2(float x0, float x1, unsigned& hi, unsigned& lo) {
    __nv_bfloat16 h0 = __float2bfloat16_rn(x0);
    __nv_bfloat16 h1 = __float2bfloat16_rn(x1);
    float r0 = x0 - __bfloat162float(h0);
    float r1 = x1 - __bfloat162float(h1);
    __nv_bfloat16 l0 = __float2bfloat16_rn(r0);
    __nv_bfloat16 l1 = __float2bfloat16_rn(r1);
    hi = (unsigned)__bfloat16_as_ushort(h0) | ((unsigned)__bfloat16_as_ushort(h1) << 16);
    lo = (unsigned)__bfloat16_as_ushort(l0) | ((unsigned)__bfloat16_as_ushort(l1) << 16);
}

// ---------------- RoPE sin/cos table --------------------------------------------
__global__ void sincos_table_kernel() {
    int idx = blockIdx.x * blockDim.x + threadIdx.x;
    if (idx >= SEQ * (HD / 2)) return;
    int pos = idx / (HD / 2);
    int j   = idx % (HD / 2);
    double inv = exp((-2.0 * (double)j / (double)HD) * log(10000.0));
    double ang = (double)pos * inv;
    float s = (float)sin(ang);
    float c = (float)cos(ang);
    g_sin[pos * HD + 2 * j]     = s;
    g_sin[pos * HD + 2 * j + 1] = s;
    g_cos[pos * HD + 2 * j]     = c;
    g_cos[pos * HD + 2 * j + 1] = c;
}

// ---------------- RoPE apply (q and k in-place) ---------------------------------
__global__ void rope_kernel() {
    int idx = blockIdx.x * blockDim.x + threadIdx.x;
    const int total = BATCH * SEQ * HID / 2;
    if (idx >= total) return;
    int pair = idx % (HID / 2);
    int row  = idx / (HID / 2);
    int s    = row % SEQ;
    int d    = (pair * 2) % HD;
    float sn = g_sin[s * HD + d];
    float cs = g_cos[s * HD + d];
    int base = row * HID + pair * 2;
    float2 q = *(float2*)&g_q[base];
    float2 k = *(float2*)&g_k[base];
    float2 qo, ko;
    qo.x = q.x * cs - q.y * sn;  qo.y = q.y * cs + q.x * sn;
    ko.x = k.x * cs - k.y * sn;  ko.y = k.y * cs + k.x * sn;
    *(float2*)&g_q[base] = qo;
    *(float2*)&g_k[base] = ko;
}

// ---------------- split A: fp32 [M,K] -> packed hi/lo [M][K/2] ------------------
__global__ void split_pairs_kernel(const float* __restrict__ src,
                                   unsigned* __restrict__ hi,
                                   unsigned* __restrict__ lo, int n) {
    int i = blockIdx.x * blockDim.x + threadIdx.x;
    if (i >= n) return;
    float2 v = *(const float2*)(src + 2 * (size_t)i);
    unsigned h, l;
    bsplit2(v.x, v.y, h, l);
    hi[i] = h; lo[i] = l;
}

// ---------------- transpose+split W: fp32 [K,N] -> packed hi/lo [N][K/2] --------
__global__ __launch_bounds__(256) void transpose_split_kernel(
    const float* __restrict__ W, unsigned* __restrict__ hiT,
    unsigned* __restrict__ loT, int K, int N)
{
    __shared__ float ts[64][33];
    const int k0 = blockIdx.y * 64, n0 = blockIdx.x * 32;
    const int tid = threadIdx.x;
#pragma unroll
    for (int j = 0; j < 8; j++) {
        int id = tid + j * 256;
        int r = id >> 5, c = id & 31;
        ts[r][c] = W[(size_t)(k0 + r) * N + n0 + c];
    }
    __syncthreads();
    const int Kp = K >> 1;
#pragma unroll
    for (int j = 0; j < 4; j++) {
        int id = tid + j * 256;          // 0..1023
        int nloc = id >> 5, kp = id & 31;
        unsigned h, l;
        bsplit2(ts[2 * kp][nloc], ts[2 * kp + 1][nloc], h, l);
        size_t o = (size_t)(n0 + nloc) * Kp + (k0 >> 1) + kp;
        hiT[o] = h; loT[o] = l;
    }
}

// ---------------- mma + cp.async helpers ----------------------------------------
__device__ __forceinline__ void mma_bf16(float c[4], const unsigned a[4],
                                         unsigned b0, unsigned b1) {
    asm volatile(
        "mma.sync.aligned.m16n8k16.row.col.f32.bf16.bf16.f32 "
        "{%0,%1,%2,%3}, {%4,%5,%6,%7}, {%8,%9}, {%0,%1,%2,%3};"
        : "+f"(c[0]), "+f"(c[1]), "+f"(c[2]), "+f"(c[3])
        : "r"(a[0]), "r"(a[1]), "r"(a[2]), "r"(a[3]), "r"(b0), "r"(b1));
}
__device__ __forceinline__ void cp_async16(unsigned saddr, const void* gptr) {
    asm volatile("cp.async.cg.shared.global [%0], [%1], 16;" :: "r"(saddr), "l"(gptr));
}

// ---------------- pre-split bf16x3 tensor GEMM ----------------------------------
// C[M,N] = A[M,K] W[K,N] + bias, operands pre-split packed bf16x2.
// CTA 128x128, 256 thr = 8 warps (4x2). Slab = 32 k = 16 kp. 3-stage cp.async.
#define GSTR 20                    // smem row stride (words): 16 kp + 4 pad
#define ARRW (128*GSTR)            // words per array (2560)
#define STGW (4*ARRW)              // words per stage (10240)
#define GEMM_SMEM_BYTES (3*STGW*4) // 122880

__global__ __launch_bounds__(256, 1) void gemm_sp_kernel(
    const unsigned* __restrict__ Ah, const unsigned* __restrict__ Al,
    const unsigned* __restrict__ Bh, const unsigned* __restrict__ Bl,
    const float* __restrict__ bias, float* __restrict__ C,
    int M, int N, int Kp)
{
    extern __shared__ unsigned sm[];
    const int tid = threadIdx.x, warp = tid >> 5, lane = tid & 31;
    const int wr = warp >> 1, wc = warp & 1;
    const int g = lane >> 2, t = lane & 3;
    const int rowBase = blockIdx.y * 128, colBase = blockIdx.x * 128;

    float acc[2][8][4];
#pragma unroll
    for (int i = 0; i < 2; i++)
#pragma unroll
        for (int j = 0; j < 8; j++)
#pragma unroll
            for (int c = 0; c < 4; c++) acc[i][j][c] = 0.f;

    // loader: 2048 16B-chunks per stage, 8 per thread
    const unsigned* gb[8];
    unsigned so[8];
#pragma unroll
    for (int j = 0; j < 8; j++) {
        int id = tid + j * 256;
        int arr = id >> 9, cid = id & 511;
        int row = cid >> 2, c4 = (cid & 3) * 4;
        const unsigned* base = (arr == 0) ? Ah : (arr == 1) ? Al : (arr == 2) ? Bh : Bl;
        int grow = (arr < 2) ? (rowBase + row) : (colBase + row);
        gb[j] = base + (size_t)grow * Kp + c4;
        so[j] = (unsigned)(arr * ARRW + row * GSTR + c4) * 4u;
    }
    const unsigned smbase = (unsigned)__cvta_generic_to_shared(sm);

    auto load_stage = [&](int kt, int st) {
        unsigned sb = smbase + (unsigned)(st * STGW) * 4u;
#pragma unroll
        for (int j = 0; j < 8; j++)
            cp_async16(sb + so[j], gb[j] + kt * 16);
        asm volatile("cp.async.commit_group;");
    };

    const int NT = Kp / 16;
    load_stage(0, 0);
    load_stage(1, 1);
    load_stage(2, 2);
    asm volatile("cp.async.wait_group 2;");
    __syncthreads();

    for (int kt = 0; kt < NT; kt++) {
        const int st = kt % 3;
        const unsigned* sAh = sm + st * STGW;
        const unsigned* sAl = sAh + ARRW;
        const unsigned* sBh = sAl + ARRW;
        const unsigned* sBl = sBh + ARRW;

#pragma unroll
        for (int kc = 0; kc < 2; kc++) {
            const int kp0 = kc * 8;
            unsigned ah[2][4], al[2][4];
#pragma unroll
            for (int mt = 0; mt < 2; mt++) {
                int r0 = (wr * 32 + mt * 16 + g) * GSTR + kp0 + t;
                ah[mt][0] = sAh[r0];
                ah[mt][1] = sAh[r0 + 8 * GSTR];
                ah[mt][2] = sAh[r0 + 4];
                ah[mt][3] = sAh[r0 + 8 * GSTR + 4];
                al[mt][0] = sAl[r0];
                al[mt][1] = sAl[r0 + 8 * GSTR];
                al[mt][2] = sAl[r0 + 4];
                al[mt][3] = sAl[r0 + 8 * GSTR + 4];
            }
#pragma unroll
            for (int nt = 0; nt < 8; nt++) {
                int nb = (wc * 64 + nt * 8 + g) * GSTR + kp0 + t;
                unsigned bh0 = sBh[nb], bh1 = sBh[nb + 4];
                unsigned bl0 = sBl[nb], bl1 = sBl[nb + 4];
#pragma unroll
                for (int mt = 0; mt < 2; mt++) {
                    mma_bf16(acc[mt][nt], ah[mt], bh0, bh1);
                    mma_bf16(acc[mt][nt], al[mt], bh0, bh1);
                    mma_bf16(acc[mt][nt], ah[mt], bl0, bl1);
                }
            }
        }

        __syncthreads();
        if (kt + 3 < NT) load_stage(kt + 3, st);
        else asm volatile("cp.async.commit_group;");
        asm volatile("cp.async.wait_group 2;");
        __syncthreads();
    }

    // epilogue: bias + store
#pragma unroll
    for (int nt = 0; nt < 8; nt++) {
        int col = colBase + wc * 64 + nt * 8 + 2 * t;
        float2 bv = *(const float2*)&bias[col];
#pragma unroll
        for (int mt = 0; mt < 2; mt++) {
            int row0 = rowBase + wr * 32 + mt * 16 + g;
            float2 v0 = make_float2(acc[mt][nt][0] + bv.x, acc[mt][nt][1] + bv.y);
            float2 v1 = make_float2(acc[mt][nt][2] + bv.x, acc[mt][nt][3] + bv.y);
            *(float2*)&C[(size_t)row0 * N + col]       = v0;
            *(float2*)&C[(size_t)(row0 + 8) * N + col] = v1;
        }
    }
}

// ---------------- TF32 helpers ---------------------------------------------------
__device__ __forceinline__ unsigned f2tf32(float f) {
    unsigned r;
    asm("cvt.rna.tf32.f32 %0, %1;" : "=r"(r) : "f"(f));
    return r;
}
__device__ __forceinline__ void mma_tf32(float c[4],
    unsigned a0, unsigned a1, unsigned a2, unsigned a3,
    unsigned b0, unsigned b1)
{
    asm volatile(
        "mma.sync.aligned.m16n8k8.row.col.f32.tf32.tf32.f32 "
        "{%0,%1,%2,%3}, {%4,%5,%6,%7}, {%8,%9}, {%0,%1,%2,%3};"
        : "+f"(c[0]), "+f"(c[1]), "+f"(c[2]), "+f"(c[3])
        : "r"(a0), "r"(a1), "r"(a2), "r"(a3), "r"(b0), "r"(b1));
}

// ---------------- Flash attention (TF32 tensor-core, online softmax) -------------
#define QROWS 128
#define KTILE 64
#define QSTR  132
#define VSTR  136
#define PSTR  68
#define FLASH_SMEM_WORDS (QROWS*QSTR + KTILE*QSTR + KTILE*VSTR + QROWS*PSTR)

__global__ __launch_bounds__(256, 1) void flash_tf32_kernel(
    const float* __restrict__ Qg, const float* __restrict__ Kg,
    const float* __restrict__ Vg, float* __restrict__ Og)
{
    extern __shared__ unsigned smu[];
    unsigned* Qs = smu;
    unsigned* Ks = Qs + QROWS * QSTR;
    unsigned* Vs = Ks + KTILE * QSTR;
    unsigned* Ps = Vs + KTILE * VSTR;

    const int tid  = threadIdx.x;
    const int warp = tid >> 5;
    const int lane = tid & 31;
    const int g    = lane >> 2;
    const int t    = lane & 3;

    const int q0   = blockIdx.x * QROWS;
    const int head = blockIdx.y;
    const int b    = blockIdx.z;
    const size_t base = ((size_t)b * SEQ) * HID + (size_t)head * HD;

    const float scale = 0.08838834764831845f;

    for (int i = tid; i < QROWS * (HD / 4); i += 256) {
        int r  = i >> 5;
        int c4 = (i & 31) * 4;
        float4 v = *(const float4*)(Qg + base + (size_t)(q0 + r) * HID + c4);
        unsigned* dst = &Qs[r * QSTR + c4];
        dst[0] = f2tf32(v.x * scale);
        dst[1] = f2tf32(v.y * scale);
        dst[2] = f2tf32(v.z * scale);
        dst[3] = f2tf32(v.w * scale);
    }

    float oacc[16][4];
#pragma unroll
    for (int i = 0; i < 16; i++)
#pragma unroll
        for (int j = 0; j < 4; j++) oacc[i][j] = 0.f;
    float m0 = -INFINITY, m1 = -INFINITY, l0 = 0.f, l1 = 0.f;

    const int rowA = 16 * warp + g;

    for (int t0 = 0; t0 < SEQ; t0 += KTILE) {
        __syncthreads();
        for (int i = tid; i < KTILE * (HD / 4); i += 256) {
            int r  = i >> 5;
            int c4 = (i & 31) * 4;
            size_t goff = base + (size_t)(t0 + r) * HID + c4;
            float4 kv = *(const float4*)(Kg + goff);
            float4 vv = *(const float4*)(Vg + goff);
            unsigned* kd = &Ks[r * QSTR + c4];
            kd[0] = f2tf32(kv.x); kd[1] = f2tf32(kv.y);
            kd[2] = f2tf32(kv.z); kd[3] = f2tf32(kv.w);
            unsigned* vd = &Vs[r * VSTR + c4];
            vd[0] = f2tf32(vv.x); vd[1] = f2tf32(vv.y);
            vd[2] = f2tf32(vv.z); vd[3] = f2tf32(vv.w);
        }
        __syncthreads();

        float sacc[8][4];
#pragma unroll
        for (int i = 0; i < 8; i++)
#pragma unroll
            for (int j = 0; j < 4; j++) sacc[i][j] = 0.f;
#pragma unroll
        for (int ks = 0; ks < 16; ks++) {
            const int k0 = ks * 8;
            unsigned a0 = Qs[rowA * QSTR + k0 + t];
            unsigned a1 = Qs[(rowA + 8) * QSTR + k0 + t];
            unsigned a2 = Qs[rowA * QSTR + k0 + t + 4];
            unsigned a3 = Qs[(rowA + 8) * QSTR + k0 + t + 4];
#pragma unroll
            for (int nt = 0; nt < 8; nt++) {
                unsigned b0 = Ks[(8 * nt + g) * QSTR + k0 + t];
                unsigned b1 = Ks[(8 * nt + g) * QSTR + k0 + t + 4];
                mma_tf32(sacc[nt], a0, a1, a2, a3, b0, b1);
            }
        }

        float mx0 = -INFINITY, mx1 = -INFINITY;
#pragma unroll
        for (int nt = 0; nt < 8; nt++) {
            mx0 = fmaxf(mx0, fmaxf(sacc[nt][0], sacc[nt][1]));
            mx1 = fmaxf(mx1, fmaxf(sacc[nt][2], sacc[nt][3]));
        }
        mx0 = fmaxf(mx0, __shfl_xor_sync(0xffffffffu, mx0, 1));
        mx0 = fmaxf(mx0, __shfl_xor_sync(0xffffffffu, mx0, 2));
        mx1 = fmaxf(mx1, __shfl_xor_sync(0xffffffffu, mx1, 1));
        mx1 = fmaxf(mx1, __shfl_xor_sync(0xffffffffu, mx1, 2));
        float mn0 = fmaxf(m0, mx0), mn1 = fmaxf(m1, mx1);
        float corr0 = __expf(m0 - mn0), corr1 = __expf(m1 - mn1);
        float sum0 = 0.f, sum1 = 0.f;
#pragma unroll
        for (int nt = 0; nt < 8; nt++) {
            float p00 = __expf(sacc[nt][0] - mn0);
            float p01 = __expf(sacc[nt][1] - mn0);
            float p10 = __expf(sacc[nt][2] - mn1);
            float p11 = __expf(sacc[nt][3] - mn1);
            sum0 += p00 + p01;
            sum1 += p10 + p11;
            unsigned* pr0 = &Ps[rowA * PSTR + 8 * nt + 2 * t];
            unsigned* pr1 = &Ps[(rowA + 8) * PSTR + 8 * nt + 2 * t];
            pr0[0] = f2tf32(p00); pr0[1] = f2tf32(p01);
            pr1[0] = f2tf32(p10); pr1[1] = f2tf32(p11);
        }
        sum0 += __shfl_xor_sync(0xffffffffu, sum0, 1);
        sum0 += __shfl_xor_sync(0xffffffffu, sum0, 2);
        sum1 += __shfl_xor_sync(0xffffffffu, sum1, 1);
        sum1 += __shfl_xor_sync(0xffffffffu, sum1, 2);
        l0 = l0 * corr0 + sum0;  m0 = mn0;
        l1 = l1 * corr1 + sum1;  m1 = mn1;
#pragma unroll
        for (int nt = 0; nt < 16; nt++) {
            oacc[nt][0] *= corr0; oacc[nt][1] *= corr0;
            oacc[nt][2] *= corr1; oacc[nt][3] *= corr1;
        }
        __syncwarp();

#pragma unroll
        for (int ks = 0; ks < 8; ks++) {
            const int k0 = ks * 8;
            unsigned a0 = Ps[rowA * PSTR + k0 + t];
            unsigned a1 = Ps[(rowA + 8) * PSTR + k0 + t];
            unsigned a2 = Ps[rowA * PSTR + k0 + t + 4];
            unsigned a3 = Ps[(rowA + 8) * PSTR + k0 + t + 4];
#pragma unroll
            for (int nt = 0; nt < 16; nt++) {
                unsigned b0 = Vs[(k0 + t) * VSTR + 8 * nt + g];
                unsigned b1 = Vs[(k0 + t + 4) * VSTR + 8 * nt + g];
                mma_tf32(oacc[nt], a0, a1, a2, a3, b0, b1);
            }
        }
    }

    const float inv0 = 1.f / l0, inv1 = 1.f / l1;
    const int grow0 = q0 + 16 * warp + g;
    const int grow1 = grow0 + 8;
#pragma unroll
    for (int nt = 0; nt < 16; nt++) {
        int col = 8 * nt + 2 * t;
        float2 v0 = make_float2(oacc[nt][0] * inv0, oacc[nt][1] * inv0);
        float2 v1 = make_float2(oacc[nt][2] * inv1, oacc[nt][3] * inv1);
        *(float2*)(Og + base + (size_t)grow0 * HID + col) = v0;
        *(float2*)(Og + base + (size_t)grow1 * HID + col) = v1;
    }
}

// ---------------- launch ---------------------------------------------------------
extern "C" void kernel_launch(void* const* d_in, const int* in_sizes, int n_in,
                              void* d_out, int out_size) {
    const float* x  = (const float*)d_in[0];
    const float* Wq = (const float*)d_in[1];
    const float* bq = (const float*)d_in[2];
    const float* Wk = (const float*)d_in[3];
    const float* bk = (const float*)d_in[4];
    const float* Wv = (const float*)d_in[5];
    const float* bv = (const float*)d_in[6];
    const float* Wo = (const float*)d_in[7];
    const float* bo = (const float*)d_in[8];
    float* out = (float*)d_out;

    float *qp, *kp, *vp, *cp;
    unsigned *ah, *al, *bh, *bl;
    cudaGetSymbolAddress((void**)&qp, g_q);
    cudaGetSymbolAddress((void**)&kp, g_k);
    cudaGetSymbolAddress((void**)&vp, g_v);
    cudaGetSymbolAddress((void**)&cp, g_ctx);
    cudaGetSymbolAddress((void**)&ah, g_ah);
    cudaGetSymbolAddress((void**)&al, g_al);
    cudaGetSymbolAddress((void**)&bh, g_bh);
    cudaGetSymbolAddress((void**)&bl, g_bl);

    cudaFuncSetAttribute(gemm_sp_kernel,
                         cudaFuncAttributeMaxDynamicSharedMemorySize, GEMM_SMEM_BYTES);

    {
        int n = SEQ * (HD / 2);
        sincos_table_kernel<<<(n + 255) / 256, 256>>>();
    }

    const int nsp = MTOT * KP;            // pairs in A
    split_pairs_kernel<<<(nsp + 255) / 256, 256>>>(x, ah, al, nsp);

    dim3 tgrid(HID / 32, HID / 64);       // (64, 32)
    dim3 ggrid(HID / 128, MTOT / 128);    // (16, 32)

    transpose_split_kernel<<<tgrid, 256>>>(Wq, bh, bl, HID, HID);
    gemm_sp_kernel<<<ggrid, 256, GEMM_SMEM_BYTES>>>(ah, al, bh, bl, bq, qp, MTOT, HID, KP);
    transpose_split_kernel<<<tgrid, 256>>>(Wk, bh, bl, HID, HID);
    gemm_sp_kernel<<<ggrid, 256, GEMM_SMEM_BYTES>>>(ah, al, bh, bl, bk, kp, MTOT, HID, KP);
    transpose_split_kernel<<<tgrid, 256>>>(Wv, bh, bl, HID, HID);
    gemm_sp_kernel<<<ggrid, 256, GEMM_SMEM_BYTES>>>(ah, al, bh, bl, bv, vp, MTOT, HID, KP);

    {
        int n = BATCH * SEQ * HID / 2;
        rope_kernel<<<(n + 255) / 256, 256>>>();
    }

    const int flash_smem = FLASH_SMEM_WORDS * (int)sizeof(unsigned);
    cudaFuncSetAttribute(flash_tf32_kernel,
                         cudaFuncAttributeMaxDynamicSharedMemorySize, flash_smem);
    flash_tf32_kernel<<<dim3(SEQ / QROWS, NH, BATCH), 256, flash_smem>>>(qp, kp, vp, cp);

    split_pairs_kernel<<<(nsp + 255) / 256, 256>>>(cp, ah, al, nsp);
    transpose_split_kernel<<<tgrid, 256>>>(Wo, bh, bl, HID, HID);
    gemm_sp_kernel<<<ggrid, 256, GEMM_SMEM_BYTES>>>(ah, al, bh, bl, bo, out, MTOT, HID, KP);
}